// round 5
// baseline (speedup 1.0000x reference)
#include <cuda_runtime.h>
#include <cuda_fp16.h>
#include <stdint.h>

#define NMAX 100000
#define EMAX 1000000
#define NTILES 128   // >= ceil(NMAX/1024)

typedef unsigned long long ull;

// ---- static device scratch ----
__device__ __align__(16) ull    g_packed[NMAX];     // count<<40 | deg_fixed(2^-28)
__device__ __align__(16) int    g_start[NMAX];
__device__ __align__(16) int    g_cursor[NMAX];
__device__ __align__(16) ull    g_status[NTILES];   // lookback: flag(2) | sum<<2
__device__ __align__(16) float  g_dinv[NMAX];
__device__ __align__(16) uint2  g_edge[EMAX];       // (src, norm bits)
__device__ __align__(16) __half2 g_Shw[NMAX * 32];  // hw scratch, fp16
__device__ __align__(16) float  g_H[2][NMAX * 64];  // h1 / h2 buffers (fp32)
__device__ __align__(16) float  g_F[NMAX];          // final gemv result
__device__ int g_is64;

// ---------------------------------------------------------------------------
// helpers
// ---------------------------------------------------------------------------
__device__ __forceinline__ int edge_at(const void* ei, int idx)
{
    if (g_is64) return (int)((const long long*)ei)[idx];
    return ((const int*)ei)[idx];
}

__device__ __forceinline__ ull ffma2(ull a, ull b, ull c)
{
    ull d;
    asm("fma.rn.f32x2 %0, %1, %2, %3;" : "=l"(d) : "l"(a), "l"(b), "l"(c));
    return d;
}

__device__ __forceinline__ ull pack2(float lo, float hi)
{
    ull d;
    asm("mov.b64 %0, {%1, %2};" : "=l"(d) : "r"(__float_as_uint(lo)), "r"(__float_as_uint(hi)));
    return d;
}

__device__ __forceinline__ float2 unpack2(ull v)
{
    unsigned lo, hi;
    asm("mov.b64 {%0, %1}, %2;" : "=r"(lo), "=r"(hi) : "l"(v));
    return make_float2(__uint_as_float(lo), __uint_as_float(hi));
}

__device__ __forceinline__ unsigned smem_u32(const void* p)
{
    unsigned a;
    asm("{ .reg .u64 t; cvta.to.shared.u64 t, %1; cvt.u32.u64 %0, t; }" : "=r"(a) : "l"(p));
    return a;
}

// ---------------------------------------------------------------------------
// init + dtype probe + status reset
// ---------------------------------------------------------------------------
__global__ void init_kernel(const void* ei, int E, int n)
{
    int i = blockIdx.x * blockDim.x + threadIdx.x;
    if (blockIdx.x == 0 && threadIdx.x < 32) {
        long long v = ((const long long*)ei)[threadIdx.x];
        unsigned ok = __ballot_sync(0xffffffffu, v >= 0 && v < (long long)n);
        if (threadIdx.x == 0) g_is64 = (ok == 0xffffffffu) ? 1 : 0;
    }
    if (i < NTILES) g_status[i] = 0;
    if (i < n) g_packed[i] = (ull)1 << 28;   // self-loop deg 1.0 in 2^-28 fixed
}

// ---------------------------------------------------------------------------
// histogram: single packed 64-bit atomic per edge
// ---------------------------------------------------------------------------
__global__ void hist_kernel(const void* __restrict__ ei,
                            const float* __restrict__ ew, int E, int n)
{
    int e = blockIdx.x * blockDim.x + threadIdx.x;
    if (e < E) {
        int c = edge_at(ei, E + e);
        if ((unsigned)c < (unsigned)n) {
            ull add = ((ull)1 << 40) + __float2ull_rn(ew[e] * 268435456.0f);
            atomicAdd(&g_packed[c], add);
        }
    }
}

// ---------------------------------------------------------------------------
// single-pass scan (decoupled lookback, tile=1024) + cursor/dinv computation
// ---------------------------------------------------------------------------
__global__ void __launch_bounds__(256) scan_kernel(int n)
{
    __shared__ int sd[256];
    __shared__ int s_excl;
    int t = threadIdx.x;
    int b = blockIdx.x;
    int base = b * 1024 + t * 4;

    int v0 = (base + 0 < n) ? (int)(g_packed[base + 0] >> 40) : 0;
    int v1 = (base + 1 < n) ? (int)(g_packed[base + 1] >> 40) : 0;
    int v2 = (base + 2 < n) ? (int)(g_packed[base + 2] >> 40) : 0;
    int v3 = (base + 3 < n) ? (int)(g_packed[base + 3] >> 40) : 0;
    int tsum = v0 + v1 + v2 + v3;
    sd[t] = tsum;
    __syncthreads();
    int x = tsum;
    for (int off = 1; off < 256; off <<= 1) {
        int y = (t >= off) ? sd[t - off] : 0;
        __syncthreads();
        x += y;
        sd[t] = x;
        __syncthreads();
    }
    int thr_excl = x - tsum;           // exclusive within tile
    int agg = sd[255];                 // tile total
    __syncthreads();

    // publish aggregate (or inclusive if tile 0)
    if (t == 0) {
        ull st = b == 0 ? (2ull | ((ull)agg << 2)) : (1ull | ((ull)agg << 2));
        atomicExch(&g_status[b], st);
    }

    // warp 0 windowed lookback
    if (t < 32) {
        int excl = 0;
        if (b > 0) {
            int j = b - 1;
            for (;;) {
                int idx = j - (int)t;       // lane t looks at tile idx
                ull st = 0;
                if (idx >= 0) {
                    do { st = atomicAdd(&g_status[idx], 0ull); } while ((st & 3ull) == 0ull);
                }
                unsigned pmask = __ballot_sync(0xffffffffu, idx >= 0 && (st & 3ull) == 2ull);
                int val = (int)(st >> 2);
                if (pmask) {
                    int lead = __ffs(pmask) - 1;   // closest inclusive-prefix tile
                    int contrib = (t <= lead && idx >= 0) ? val : 0;
                    for (int o = 16; o; o >>= 1) contrib += __shfl_xor_sync(0xffffffffu, contrib, o);
                    excl += contrib;
                    break;
                } else {
                    int contrib = (idx >= 0) ? val : 0;
                    for (int o = 16; o; o >>= 1) contrib += __shfl_xor_sync(0xffffffffu, contrib, o);
                    excl += contrib;
                    j -= 32;
                }
            }
            if (t == 0) atomicExch(&g_status[b], 2ull | ((ull)(excl + agg) << 2));
        }
        if (t == 0) s_excl = excl;
    }
    __syncthreads();

    int run = s_excl + thr_excl;
    if (base < n) {
#pragma unroll
        for (int q = 0; q < 4; q++) {
            int i = base + q;
            if (i < n) {
                g_start[i] = run;
                g_cursor[i] = run;
                ull pk = g_packed[i];
                float deg = (float)(pk & (((ull)1 << 40) - 1)) * (1.0f / 268435456.0f);
                g_dinv[i] = rsqrtf(deg);
                run += (int)(pk >> 40);
            }
        }
    }
}

__global__ void build_kernel(const void* __restrict__ ei,
                             const float* __restrict__ ew, int E, int n)
{
    int e = blockIdx.x * blockDim.x + threadIdx.x;
    if (e < E) {
        int r = edge_at(ei, e);
        int c = edge_at(ei, E + e);
        if ((unsigned)r < (unsigned)n && (unsigned)c < (unsigned)n) {
            float nm = g_dinv[r] * ew[e] * g_dinv[c];
            int p = atomicAdd(&g_cursor[c], 1);
            if ((unsigned)p < (unsigned)EMAX)
                g_edge[p] = make_uint2((unsigned)r, __float_as_uint(nm));
        }
    }
}

// ---------------------------------------------------------------------------
// Dense GEMM via packed f32x2: g_Shw = (hext or g_H[src]) @ W, fp16 output
// ---------------------------------------------------------------------------
__global__ void __launch_bounds__(256) gemm64_kernel(const float* __restrict__ hext,
                                                     int src,
                                                     const float* __restrict__ W, int n)
{
    __shared__ float sW[4096];
    for (int i = threadIdx.x; i < 4096; i += 256) sW[i] = W[i];
    __syncthreads();
    int row = blockIdx.x * 256 + threadIdx.x;
    if (row >= n) return;

    const float* h = hext ? hext : g_H[src];
    const float4* hr = reinterpret_cast<const float4*>(h + (size_t)row * 64);
    unsigned swaddr = smem_u32(sW);

    ull acc[32];
#pragma unroll
    for (int j = 0; j < 32; j++) acc[j] = 0ull;

    for (int k4 = 0; k4 < 16; k4++) {
        float4 xv = __ldg(hr + k4);
#pragma unroll
        for (int kk = 0; kk < 4; kk++) {
            float xk = (kk == 0) ? xv.x : (kk == 1) ? xv.y : (kk == 2) ? xv.z : xv.w;
            ull x2 = pack2(xk, xk);
            unsigned wrow = swaddr + (unsigned)(k4 * 4 + kk) * 256;
#pragma unroll
            for (int j = 0; j < 16; j++) {
                ull w01, w23;
                asm("ld.shared.v2.u64 {%0, %1}, [%2];"
                    : "=l"(w01), "=l"(w23) : "r"(wrow + j * 16));
                acc[2 * j]     = ffma2(x2, w01, acc[2 * j]);
                acc[2 * j + 1] = ffma2(x2, w23, acc[2 * j + 1]);
            }
        }
    }

    unsigned hu[32];
#pragma unroll
    for (int j = 0; j < 32; j++) {
        float2 p = unpack2(acc[j]);
        __half2 hh = __floats2half2_rn(p.x, p.y);
        hu[j] = *reinterpret_cast<unsigned*>(&hh);
    }
    uint4* o = reinterpret_cast<uint4*>(g_Shw + (size_t)row * 32);
#pragma unroll
    for (int q = 0; q < 8; q++)
        o[q] = make_uint4(hu[4 * q], hu[4 * q + 1], hu[4 * q + 2], hu[4 * q + 3]);
}

// ---------------------------------------------------------------------------
// Aggregation core: fully-masked unroll-8 — every chunk issues 8 concurrent
// gathers (clamped index, zeroed weight) so a degree<=8*k node takes k epochs.
// ---------------------------------------------------------------------------
__device__ __forceinline__ float2 agg_node(int i, int lane)
{
    float di = g_dinv[i];
    float selfn = di * di;
    float2 v = __half22float2(g_Shw[(size_t)i * 32 + lane]);
    float ax = selfn * v.x, ay = selfn * v.y;

    int e0 = g_start[i];
    int cnt = (int)(g_packed[i] >> 40);
    int end = e0 + cnt;

    float bx0 = 0.f, by0 = 0.f, bx1 = 0.f, by1 = 0.f;
    float bx2 = 0.f, by2 = 0.f, bx3 = 0.f, by3 = 0.f;

    for (int e = e0; e < end; e += 8) {
#pragma unroll
        for (int q = 0; q < 8; q++) {
            int idx = e + q;
            bool ok = idx < end;
            uint2 ed = g_edge[ok ? idx : e0];          // e0 always valid if cnt>0
            float nm = ok ? __uint_as_float(ed.y) : 0.f;
            float2 vv = __half22float2(g_Shw[(size_t)ed.x * 32 + lane]);
            if (q == 0 || q == 4) { bx0 += nm * vv.x; by0 += nm * vv.y; }
            if (q == 1 || q == 5) { bx1 += nm * vv.x; by1 += nm * vv.y; }
            if (q == 2 || q == 6) { bx2 += nm * vv.x; by2 += nm * vv.y; }
            if (q == 3 || q == 7) { bx3 += nm * vv.x; by3 += nm * vv.y; }
        }
    }
    ax += (bx0 + bx1) + (bx2 + bx3);
    ay += (by0 + by1) + (by2 + by3);
    return make_float2(ax, ay);
}

// layers 1,2: write fp32 h to g_H[dst]
__global__ void __launch_bounds__(512) agg_kernel(const float* __restrict__ bias,
                                                  int resid, int dst, int n)
{
    int wid = (blockIdx.x * blockDim.x + threadIdx.x) >> 5;
    int lane = threadIdx.x & 31;
    if (wid >= n) return;

    float2 a = agg_node(wid, lane);
    float2 bb = reinterpret_cast<const float2*>(bias)[lane];
    a.x += bb.x; a.y += bb.y;
    if (resid >= 0) {
        float2 r = reinterpret_cast<const float2*>(g_H[resid])[(size_t)wid * 32 + lane];
        a.x += r.x; a.y += r.y;
    }
    a.x = fmaxf(a.x, 0.f); a.y = fmaxf(a.y, 0.f);
    reinterpret_cast<float2*>(g_H[dst])[(size_t)wid * 32 + lane] = a;
}

// layer 3 fused with final GEMV: F[i] = relu(agg + b2 + h2) . Wf
__global__ void __launch_bounds__(512) agg3_kernel(const float* __restrict__ bias,
                                                   int resid,
                                                   const float* __restrict__ Wf, int n)
{
    int wid = (blockIdx.x * blockDim.x + threadIdx.x) >> 5;
    int lane = threadIdx.x & 31;
    if (wid >= n) return;

    float2 a = agg_node(wid, lane);
    float2 bb = reinterpret_cast<const float2*>(bias)[lane];
    a.x += bb.x; a.y += bb.y;
    if (resid >= 0) {
        float2 r = reinterpret_cast<const float2*>(g_H[resid])[(size_t)wid * 32 + lane];
        a.x += r.x; a.y += r.y;
    }
    a.x = fmaxf(a.x, 0.f); a.y = fmaxf(a.y, 0.f);

    float2 wf = reinterpret_cast<const float2*>(Wf)[lane];
    float p = a.x * wf.x + a.y * wf.y;
#pragma unroll
    for (int o = 16; o; o >>= 1) p += __shfl_xor_sync(0xffffffffu, p, o);
    if (lane == 0) g_F[wid] = p;
}

// ---------------------------------------------------------------------------
// Final scalar aggregation: out[i] = sum_e nm*F[src] + dinv^2*F[i] + bf
// ---------------------------------------------------------------------------
__global__ void agg_final_kernel(const float* __restrict__ bf,
                                 float* __restrict__ out, int n)
{
    int i = blockIdx.x * blockDim.x + threadIdx.x;
    if (i >= n) return;
    float di = g_dinv[i];
    float acc = di * di * g_F[i];
    int e0 = g_start[i];
    int end = e0 + (int)(g_packed[i] >> 40);
    float a0 = 0.f, a1 = 0.f, a2 = 0.f, a3 = 0.f;
    for (int e = e0; e < end; e += 8) {
#pragma unroll
        for (int q = 0; q < 8; q++) {
            int idx = e + q;
            bool ok = idx < end;
            uint2 ed = g_edge[ok ? idx : e0];
            float nm = ok ? __uint_as_float(ed.y) : 0.f;
            float fv = g_F[ed.x];
            if (q == 0 || q == 4) a0 += nm * fv;
            if (q == 1 || q == 5) a1 += nm * fv;
            if (q == 2 || q == 6) a2 += nm * fv;
            if (q == 3 || q == 7) a3 += nm * fv;
        }
    }
    out[i] = acc + (a0 + a1) + (a2 + a3) + bf[0];
}

// ---------------------------------------------------------------------------
// Launch
// ---------------------------------------------------------------------------
extern "C" void kernel_launch(void* const* d_in, const int* in_sizes, int n_in,
                              void* d_out, int out_size)
{
    const float* x    = (const float*)d_in[0];
    const void*  ei   = d_in[1];
    const float* ew   = (const float*)d_in[2];
    const float* W_in = (const float*)d_in[4];
    const float* b_in = (const float*)d_in[5];
    const float* W1   = (const float*)d_in[6];
    const float* b1   = (const float*)d_in[7];
    const float* W2   = (const float*)d_in[8];
    const float* b2   = (const float*)d_in[9];
    const float* Wf   = (const float*)d_in[10];
    const float* bf   = (const float*)d_in[11];
    float* out = (float*)d_out;

    int n = in_sizes[0] / 64;
    int E = in_sizes[2];

    int nbN  = (n + 255) / 256;
    int nbE  = (E + 255) / 256;
    int nbSc = (n + 1023) / 1024;     // <= NTILES
    int nbAg = (n + 15) / 16;         // warp per node, 16 warps/block
    int nbGm = (n + 255) / 256;

    // --- probe + norm + CSR build (gemm1 hoisted to launch idx 3 for ncu) ---
    init_kernel<<<nbN, 256>>>(ei, E, n);
    hist_kernel<<<nbE, 256>>>(ei, ew, E, n);
    scan_kernel<<<nbSc, 256>>>(n);
    gemm64_kernel<<<nbGm, 256>>>(x, 0, W_in, n);     // layer-1 GEMM (CSR-independent)
    build_kernel<<<nbE, 256>>>(ei, ew, E, n);

    // --- layer 1: h1 = relu(conv(x)) -> H[0] ---
    agg_kernel<<<nbAg, 512>>>(b_in, -1, 0, n);

    // --- layer 2: h2 = relu(conv(h1) + h1) -> H[1] ---
    gemm64_kernel<<<nbGm, 256>>>(nullptr, 0, W1, n);
    agg_kernel<<<nbAg, 512>>>(b1, 0, 1, n);

    // --- layer 3 + final gemv: F = (relu(conv(h2)+h2)) @ Wf ---
    gemm64_kernel<<<nbGm, 256>>>(nullptr, 1, W2, n);
    agg3_kernel<<<nbAg, 512>>>(b2, 1, Wf, n);

    // --- final aggregation ---
    agg_final_kernel<<<nbN, 256>>>(bf, out, n);
}

// round 6
// speedup vs baseline: 1.0842x; 1.0842x over previous
#include <cuda_runtime.h>
#include <cuda_fp16.h>
#include <mma.h>
#include <stdint.h>

using namespace nvcuda;

#define NMAX 100000
#define EMAX 1000000
#define NTILES 128   // >= ceil(NMAX/1024)
#define NPAD (NMAX + 128)

typedef unsigned long long ull;

// ---- static device scratch ----
__device__ __align__(16) ull    g_packed[NMAX];     // count<<40 | deg_fixed(2^-28)
__device__ __align__(16) int    g_start[NMAX];
__device__ __align__(16) int    g_cursor[NMAX];
__device__ __align__(16) ull    g_status[NTILES];   // lookback: flag(2) | sum<<2
__device__ __align__(16) float  g_dinv[NMAX];
__device__ __align__(16) uint2  g_edge[EMAX];       // (src, norm bits)
__device__ __align__(16) __half g_Hh[NPAD * 64];    // fp16 h (GEMM A input)
__device__ __align__(16) __half2 g_Shw[NPAD * 32];  // hw = h@W scratch, fp16
__device__ __align__(16) float  g_H[2][NMAX * 64];  // h1 / h2 fp32 (residuals)
__device__ __align__(16) float  g_F[NMAX];          // final gemv result
__device__ int g_is64;

// ---------------------------------------------------------------------------
__device__ __forceinline__ int edge_at(const void* ei, int idx)
{
    if (g_is64) return (int)((const long long*)ei)[idx];
    return ((const int*)ei)[idx];
}

// ---------------------------------------------------------------------------
// x (fp32) -> g_Hh (fp16)
// ---------------------------------------------------------------------------
__global__ void convert_kernel(const float* __restrict__ x, int total4)
{
    int i = blockIdx.x * blockDim.x + threadIdx.x;   // one float4 -> one uint2
    if (i < total4) {
        float4 v = reinterpret_cast<const float4*>(x)[i];
        __half2 lo = __floats2half2_rn(v.x, v.y);
        __half2 hi = __floats2half2_rn(v.z, v.w);
        uint2 o;
        o.x = *reinterpret_cast<unsigned*>(&lo);
        o.y = *reinterpret_cast<unsigned*>(&hi);
        reinterpret_cast<uint2*>(g_Hh)[i] = o;
    }
}

// ---------------------------------------------------------------------------
// init + dtype probe + status reset
// ---------------------------------------------------------------------------
__global__ void init_kernel(const void* ei, int E, int n)
{
    int i = blockIdx.x * blockDim.x + threadIdx.x;
    if (blockIdx.x == 0 && threadIdx.x < 32) {
        long long v = ((const long long*)ei)[threadIdx.x];
        unsigned ok = __ballot_sync(0xffffffffu, v >= 0 && v < (long long)n);
        if (threadIdx.x == 0) g_is64 = (ok == 0xffffffffu) ? 1 : 0;
    }
    if (i < NTILES) g_status[i] = 0;
    if (i < n) g_packed[i] = (ull)1 << 28;   // self-loop deg 1.0 in 2^-28 fixed
}

__global__ void hist_kernel(const void* __restrict__ ei,
                            const float* __restrict__ ew, int E, int n)
{
    int e = blockIdx.x * blockDim.x + threadIdx.x;
    if (e < E) {
        int c = edge_at(ei, E + e);
        if ((unsigned)c < (unsigned)n) {
            ull add = ((ull)1 << 40) + __float2ull_rn(ew[e] * 268435456.0f);
            atomicAdd(&g_packed[c], add);
        }
    }
}

// ---------------------------------------------------------------------------
// single-pass scan (decoupled lookback, tile=1024) + cursor/dinv
// ---------------------------------------------------------------------------
__global__ void __launch_bounds__(256) scan_kernel(int n)
{
    __shared__ int sd[256];
    __shared__ int s_excl;
    int t = threadIdx.x;
    int b = blockIdx.x;
    int base = b * 1024 + t * 4;

    int v0 = (base + 0 < n) ? (int)(g_packed[base + 0] >> 40) : 0;
    int v1 = (base + 1 < n) ? (int)(g_packed[base + 1] >> 40) : 0;
    int v2 = (base + 2 < n) ? (int)(g_packed[base + 2] >> 40) : 0;
    int v3 = (base + 3 < n) ? (int)(g_packed[base + 3] >> 40) : 0;
    int tsum = v0 + v1 + v2 + v3;
    sd[t] = tsum;
    __syncthreads();
    int x = tsum;
    for (int off = 1; off < 256; off <<= 1) {
        int y = (t >= off) ? sd[t - off] : 0;
        __syncthreads();
        x += y;
        sd[t] = x;
        __syncthreads();
    }
    int thr_excl = x - tsum;
    int agg = sd[255];
    __syncthreads();

    if (t == 0) {
        ull st = b == 0 ? (2ull | ((ull)agg << 2)) : (1ull | ((ull)agg << 2));
        atomicExch(&g_status[b], st);
    }

    if (t < 32) {
        int excl = 0;
        if (b > 0) {
            int j = b - 1;
            for (;;) {
                int idx = j - (int)t;
                ull st = 0;
                if (idx >= 0) {
                    do { st = atomicAdd(&g_status[idx], 0ull); } while ((st & 3ull) == 0ull);
                }
                unsigned pmask = __ballot_sync(0xffffffffu, idx >= 0 && (st & 3ull) == 2ull);
                int val = (int)(st >> 2);
                if (pmask) {
                    int lead = __ffs(pmask) - 1;
                    int contrib = (t <= lead && idx >= 0) ? val : 0;
                    for (int o = 16; o; o >>= 1) contrib += __shfl_xor_sync(0xffffffffu, contrib, o);
                    excl += contrib;
                    break;
                } else {
                    int contrib = (idx >= 0) ? val : 0;
                    for (int o = 16; o; o >>= 1) contrib += __shfl_xor_sync(0xffffffffu, contrib, o);
                    excl += contrib;
                    j -= 32;
                }
            }
            if (t == 0) atomicExch(&g_status[b], 2ull | ((ull)(excl + agg) << 2));
        }
        if (t == 0) s_excl = excl;
    }
    __syncthreads();

    int run = s_excl + thr_excl;
    if (base < n) {
#pragma unroll
        for (int q = 0; q < 4; q++) {
            int i = base + q;
            if (i < n) {
                g_start[i] = run;
                g_cursor[i] = run;
                ull pk = g_packed[i];
                float deg = (float)(pk & (((ull)1 << 40) - 1)) * (1.0f / 268435456.0f);
                g_dinv[i] = rsqrtf(deg);
                run += (int)(pk >> 40);
            }
        }
    }
}

__global__ void build_kernel(const void* __restrict__ ei,
                             const float* __restrict__ ew, int E, int n)
{
    int e = blockIdx.x * blockDim.x + threadIdx.x;
    if (e < E) {
        int r = edge_at(ei, e);
        int c = edge_at(ei, E + e);
        if ((unsigned)r < (unsigned)n && (unsigned)c < (unsigned)n) {
            float nm = g_dinv[r] * ew[e] * g_dinv[c];
            int p = atomicAdd(&g_cursor[c], 1);
            if ((unsigned)p < (unsigned)EMAX)
                g_edge[p] = make_uint2((unsigned)r, __float_as_uint(nm));
        }
    }
}

// ---------------------------------------------------------------------------
// Tensor-core GEMM: g_Shw[0:128*blk] = g_Hh @ W  (fp16 x fp16 -> fp32 -> fp16)
// block = 256 threads = 8 warps; warp computes a 16x64 strip.
// ---------------------------------------------------------------------------
__global__ void __launch_bounds__(256) gemm_wmma_kernel(const float* __restrict__ W)
{
    __shared__ __half sW[64 * 64];
    __shared__ float stage[8][16 * 64];

    int t = threadIdx.x;
    for (int i = t; i < 4096; i += 256) sW[i] = __float2half(W[i]);
    __syncthreads();

    int warp = t >> 5;
    int lane = t & 31;
    int row0 = blockIdx.x * 128 + warp * 16;

    wmma::fragment<wmma::accumulator, 16, 16, 16, float> c[4];
#pragma unroll
    for (int j = 0; j < 4; j++) wmma::fill_fragment(c[j], 0.0f);

#pragma unroll
    for (int k = 0; k < 4; k++) {
        wmma::fragment<wmma::matrix_a, 16, 16, 16, __half, wmma::row_major> a;
        wmma::load_matrix_sync(a, g_Hh + (size_t)row0 * 64 + k * 16, 64);
#pragma unroll
        for (int j = 0; j < 4; j++) {
            wmma::fragment<wmma::matrix_b, 16, 16, 16, __half, wmma::row_major> b;
            wmma::load_matrix_sync(b, sW + (k * 16) * 64 + j * 16, 64);
            wmma::mma_sync(c[j], a, b, c[j]);
        }
    }

#pragma unroll
    for (int j = 0; j < 4; j++)
        wmma::store_matrix_sync(&stage[warp][j * 16], c[j], 64, wmma::mem_row_major);
    __syncwarp();

    // convert 16x64 fp32 strip -> fp16; lane handles row=lane/2, 32 cols
    int r = lane >> 1;
    int cb = (lane & 1) * 32;
    const float* src = &stage[warp][r * 64 + cb];
    uint4* dst = reinterpret_cast<uint4*>(g_Shw + (size_t)(row0 + r) * 32 + (cb >> 1));
#pragma unroll
    for (int q = 0; q < 4; q++) {
        __half2 h0 = __floats2half2_rn(src[8 * q + 0], src[8 * q + 1]);
        __half2 h1 = __floats2half2_rn(src[8 * q + 2], src[8 * q + 3]);
        __half2 h2 = __floats2half2_rn(src[8 * q + 4], src[8 * q + 5]);
        __half2 h3 = __floats2half2_rn(src[8 * q + 6], src[8 * q + 7]);
        dst[q] = make_uint4(*reinterpret_cast<unsigned*>(&h0),
                            *reinterpret_cast<unsigned*>(&h1),
                            *reinterpret_cast<unsigned*>(&h2),
                            *reinterpret_cast<unsigned*>(&h3));
    }
}

// ---------------------------------------------------------------------------
// Aggregation core (R4 style): warp/node, unroll-4 + remainder.
// ---------------------------------------------------------------------------
__device__ __forceinline__ float2 agg_node(int i, int lane)
{
    float di = g_dinv[i];
    float selfn = di * di;
    float2 v = __half22float2(g_Shw[(size_t)i * 32 + lane]);
    float ax = selfn * v.x, ay = selfn * v.y;
    float a1x = 0.f, a1y = 0.f, a2x = 0.f, a2y = 0.f, a3x = 0.f, a3y = 0.f;

    int e = g_start[i];
    int end = e + (int)(g_packed[i] >> 40);
    for (; e + 4 <= end; e += 4) {
        uint2 e0 = g_edge[e], e1 = g_edge[e + 1], e2 = g_edge[e + 2], e3 = g_edge[e + 3];
        float2 v0 = __half22float2(g_Shw[(size_t)e0.x * 32 + lane]);
        float2 v1 = __half22float2(g_Shw[(size_t)e1.x * 32 + lane]);
        float2 v2 = __half22float2(g_Shw[(size_t)e2.x * 32 + lane]);
        float2 v3 = __half22float2(g_Shw[(size_t)e3.x * 32 + lane]);
        float n0 = __uint_as_float(e0.y), n1 = __uint_as_float(e1.y);
        float n2 = __uint_as_float(e2.y), n3 = __uint_as_float(e3.y);
        ax  += n0 * v0.x; ay  += n0 * v0.y;
        a1x += n1 * v1.x; a1y += n1 * v1.y;
        a2x += n2 * v2.x; a2y += n2 * v2.y;
        a3x += n3 * v3.x; a3y += n3 * v3.y;
    }
    for (; e < end; e++) {
        uint2 e0 = g_edge[e];
        float2 v0 = __half22float2(g_Shw[(size_t)e0.x * 32 + lane]);
        float n0 = __uint_as_float(e0.y);
        ax += n0 * v0.x; ay += n0 * v0.y;
    }
    ax += a1x + a2x + a3x;
    ay += a1y + a2y + a3y;
    return make_float2(ax, ay);
}

// layers 1,2: write fp32 h to g_H[dst] AND fp16 h to g_Hh (next GEMM's A)
__global__ void __launch_bounds__(256) agg_kernel(const float* __restrict__ bias,
                                                  int resid, int dst, int n)
{
    int wid = (blockIdx.x * blockDim.x + threadIdx.x) >> 5;
    int lane = threadIdx.x & 31;
    if (wid >= n) return;

    float2 a = agg_node(wid, lane);
    float2 bb = reinterpret_cast<const float2*>(bias)[lane];
    a.x += bb.x; a.y += bb.y;
    if (resid >= 0) {
        float2 r = reinterpret_cast<const float2*>(g_H[resid])[(size_t)wid * 32 + lane];
        a.x += r.x; a.y += r.y;
    }
    a.x = fmaxf(a.x, 0.f); a.y = fmaxf(a.y, 0.f);
    reinterpret_cast<float2*>(g_H[dst])[(size_t)wid * 32 + lane] = a;
    __half2 hh = __floats2half2_rn(a.x, a.y);
    reinterpret_cast<__half2*>(g_Hh)[(size_t)wid * 32 + lane] = hh;
}

// layer 3 fused with final GEMV: F[i] = relu(agg + b2 + h2) . Wf
__global__ void __launch_bounds__(256) agg3_kernel(const float* __restrict__ bias,
                                                   int resid,
                                                   const float* __restrict__ Wf, int n)
{
    int wid = (blockIdx.x * blockDim.x + threadIdx.x) >> 5;
    int lane = threadIdx.x & 31;
    if (wid >= n) return;

    float2 a = agg_node(wid, lane);
    float2 bb = reinterpret_cast<const float2*>(bias)[lane];
    a.x += bb.x; a.y += bb.y;
    if (resid >= 0) {
        float2 r = reinterpret_cast<const float2*>(g_H[resid])[(size_t)wid * 32 + lane];
        a.x += r.x; a.y += r.y;
    }
    a.x = fmaxf(a.x, 0.f); a.y = fmaxf(a.y, 0.f);

    float2 wf = reinterpret_cast<const float2*>(Wf)[lane];
    float p = a.x * wf.x + a.y * wf.y;
#pragma unroll
    for (int o = 16; o; o >>= 1) p += __shfl_xor_sync(0xffffffffu, p, o);
    if (lane == 0) g_F[wid] = p;
}

// ---------------------------------------------------------------------------
// Final scalar aggregation
// ---------------------------------------------------------------------------
__global__ void agg_final_kernel(const float* __restrict__ bf,
                                 float* __restrict__ out, int n)
{
    int i = blockIdx.x * blockDim.x + threadIdx.x;
    if (i >= n) return;
    float di = g_dinv[i];
    float acc = di * di * g_F[i];
    float a1 = 0.f, a2 = 0.f, a3 = 0.f;
    int e = g_start[i];
    int end = e + (int)(g_packed[i] >> 40);
    for (; e + 4 <= end; e += 4) {
        uint2 e0 = g_edge[e], e1 = g_edge[e + 1], e2 = g_edge[e + 2], e3 = g_edge[e + 3];
        acc += __uint_as_float(e0.y) * g_F[e0.x];
        a1  += __uint_as_float(e1.y) * g_F[e1.x];
        a2  += __uint_as_float(e2.y) * g_F[e2.x];
        a3  += __uint_as_float(e3.y) * g_F[e3.x];
    }
    for (; e < end; e++) {
        uint2 e0 = g_edge[e];
        acc += __uint_as_float(e0.y) * g_F[e0.x];
    }
    out[i] = acc + a1 + a2 + a3 + bf[0];
}

// ---------------------------------------------------------------------------
// Launch
// ---------------------------------------------------------------------------
extern "C" void kernel_launch(void* const* d_in, const int* in_sizes, int n_in,
                              void* d_out, int out_size)
{
    const float* x    = (const float*)d_in[0];
    const void*  ei   = d_in[1];
    const float* ew   = (const float*)d_in[2];
    const float* W_in = (const float*)d_in[4];
    const float* b_in = (const float*)d_in[5];
    const float* W1   = (const float*)d_in[6];
    const float* b1   = (const float*)d_in[7];
    const float* W2   = (const float*)d_in[8];
    const float* b2   = (const float*)d_in[9];
    const float* Wf   = (const float*)d_in[10];
    const float* bf   = (const float*)d_in[11];
    float* out = (float*)d_out;

    int n = in_sizes[0] / 64;
    int E = in_sizes[2];

    int nbN  = (n + 255) / 256;
    int nbE  = (E + 255) / 256;
    int nbSc = (n + 1023) / 1024;       // <= NTILES
    int nbAg = (n + 7) / 8;             // warp per node, 8 warps/block
    int nbCv = (n * 16 + 255) / 256;    // float4 units
    int nbGw = (n + 127) / 128;         // wmma: 128 rows/block

    // --- ordering: wmma GEMM at launch idx 3 for ncu capture ---
    convert_kernel<<<nbCv, 256>>>(x, n * 16);            // 0: x -> fp16
    init_kernel<<<nbN, 256>>>(ei, E, n);                 // 1
    hist_kernel<<<nbE, 256>>>(ei, ew, E, n);             // 2
    gemm_wmma_kernel<<<nbGw, 256>>>(W_in);               // 3: layer-1 GEMM
    scan_kernel<<<nbSc, 256>>>(n);                       // 4
    build_kernel<<<nbE, 256>>>(ei, ew, E, n);            // 5

    // --- layer 1: h1 = relu(conv(x)) -> H[0], g_Hh ---
    agg_kernel<<<nbAg, 256>>>(b_in, -1, 0, n);

    // --- layer 2: h2 = relu(conv(h1) + h1) -> H[1], g_Hh ---
    gemm_wmma_kernel<<<nbGw, 256>>>(W1);
    agg_kernel<<<nbAg, 256>>>(b1, 0, 1, n);

    // --- layer 3 + final gemv: F = relu(conv(h2)+h2) . Wf ---
    gemm_wmma_kernel<<<nbGw, 256>>>(W2);
    agg3_kernel<<<nbAg, 256>>>(b2, 1, Wf, n);

    // --- final aggregation ---
    agg_final_kernel<<<nbN, 256>>>(bf, out, n);
}

// round 7
// speedup vs baseline: 1.2974x; 1.1966x over previous
#include <cuda_runtime.h>
#include <cuda_fp16.h>
#include <mma.h>
#include <stdint.h>

using namespace nvcuda;

#define NMAX 100000
#define EMAX 1000000
#define NTILES 128   // >= ceil(NMAX/1024)
#define NPAD (NMAX + 128)

typedef unsigned long long ull;

// ---- static device scratch ----
__device__ __align__(16) ull    g_packed[NMAX];     // count<<40 | deg_fixed(2^-28)
__device__ __align__(16) int    g_start[NMAX];
__device__ __align__(16) int    g_cursor[NMAX];
__device__ __align__(16) ull    g_status[NTILES];   // lookback: flag(2) | sum<<2
__device__ __align__(16) float  g_dinv[NMAX];
__device__ __align__(16) uint2  g_edge[EMAX];       // (src, norm bits)
__device__ __align__(16) __half g_Hh[NPAD * 64];    // fp16 h (GEMM A input)
__device__ __align__(16) float  g_S[NPAD * 64];     // hw = h@W, fp32 (GEMM C output)
__device__ __align__(16) float  g_H[2][NMAX * 64];  // h1 / h2 fp32 (residuals)
__device__ __align__(16) float  g_F[NMAX];          // final gemv result
__device__ int g_is64;

// ---------------------------------------------------------------------------
__device__ __forceinline__ int edge_at(const void* ei, int idx)
{
    if (g_is64) return (int)((const long long*)ei)[idx];
    return ((const int*)ei)[idx];
}

// ---------------------------------------------------------------------------
// x (fp32) -> g_Hh (fp16)
// ---------------------------------------------------------------------------
__global__ void convert_kernel(const float* __restrict__ x, int total4)
{
    int i = blockIdx.x * blockDim.x + threadIdx.x;   // one float4 -> one uint2
    if (i < total4) {
        float4 v = reinterpret_cast<const float4*>(x)[i];
        __half2 lo = __floats2half2_rn(v.x, v.y);
        __half2 hi = __floats2half2_rn(v.z, v.w);
        uint2 o;
        o.x = *reinterpret_cast<unsigned*>(&lo);
        o.y = *reinterpret_cast<unsigned*>(&hi);
        reinterpret_cast<uint2*>(g_Hh)[i] = o;
    }
}

// ---------------------------------------------------------------------------
// init + dtype probe + status reset
// ---------------------------------------------------------------------------
__global__ void init_kernel(const void* ei, int E, int n)
{
    int i = blockIdx.x * blockDim.x + threadIdx.x;
    if (blockIdx.x == 0 && threadIdx.x < 32) {
        long long v = ((const long long*)ei)[threadIdx.x];
        unsigned ok = __ballot_sync(0xffffffffu, v >= 0 && v < (long long)n);
        if (threadIdx.x == 0) g_is64 = (ok == 0xffffffffu) ? 1 : 0;
    }
    if (i < NTILES) g_status[i] = 0;
    if (i < n) g_packed[i] = (ull)1 << 28;   // self-loop deg 1.0 in 2^-28 fixed
}

__global__ void hist_kernel(const void* __restrict__ ei,
                            const float* __restrict__ ew, int E, int n)
{
    int e = blockIdx.x * blockDim.x + threadIdx.x;
    if (e < E) {
        int c = edge_at(ei, E + e);
        if ((unsigned)c < (unsigned)n) {
            ull add = ((ull)1 << 40) + __float2ull_rn(ew[e] * 268435456.0f);
            atomicAdd(&g_packed[c], add);
        }
    }
}

// ---------------------------------------------------------------------------
// single-pass scan (decoupled lookback, tile=1024) + cursor/dinv
// ---------------------------------------------------------------------------
__global__ void __launch_bounds__(256) scan_kernel(int n)
{
    __shared__ int sd[256];
    __shared__ int s_excl;
    int t = threadIdx.x;
    int b = blockIdx.x;
    int base = b * 1024 + t * 4;

    int v0 = (base + 0 < n) ? (int)(g_packed[base + 0] >> 40) : 0;
    int v1 = (base + 1 < n) ? (int)(g_packed[base + 1] >> 40) : 0;
    int v2 = (base + 2 < n) ? (int)(g_packed[base + 2] >> 40) : 0;
    int v3 = (base + 3 < n) ? (int)(g_packed[base + 3] >> 40) : 0;
    int tsum = v0 + v1 + v2 + v3;
    sd[t] = tsum;
    __syncthreads();
    int x = tsum;
    for (int off = 1; off < 256; off <<= 1) {
        int y = (t >= off) ? sd[t - off] : 0;
        __syncthreads();
        x += y;
        sd[t] = x;
        __syncthreads();
    }
    int thr_excl = x - tsum;
    int agg = sd[255];
    __syncthreads();

    if (t == 0) {
        ull st = b == 0 ? (2ull | ((ull)agg << 2)) : (1ull | ((ull)agg << 2));
        atomicExch(&g_status[b], st);
    }

    if (t < 32) {
        int excl = 0;
        if (b > 0) {
            int j = b - 1;
            for (;;) {
                int idx = j - (int)t;
                ull st = 0;
                if (idx >= 0) {
                    do { st = atomicAdd(&g_status[idx], 0ull); } while ((st & 3ull) == 0ull);
                }
                unsigned pmask = __ballot_sync(0xffffffffu, idx >= 0 && (st & 3ull) == 2ull);
                int val = (int)(st >> 2);
                if (pmask) {
                    int lead = __ffs(pmask) - 1;
                    int contrib = (t <= lead && idx >= 0) ? val : 0;
                    for (int o = 16; o; o >>= 1) contrib += __shfl_xor_sync(0xffffffffu, contrib, o);
                    excl += contrib;
                    break;
                } else {
                    int contrib = (idx >= 0) ? val : 0;
                    for (int o = 16; o; o >>= 1) contrib += __shfl_xor_sync(0xffffffffu, contrib, o);
                    excl += contrib;
                    j -= 32;
                }
            }
            if (t == 0) atomicExch(&g_status[b], 2ull | ((ull)(excl + agg) << 2));
        }
        if (t == 0) s_excl = excl;
    }
    __syncthreads();

    int run = s_excl + thr_excl;
    if (base < n) {
#pragma unroll
        for (int q = 0; q < 4; q++) {
            int i = base + q;
            if (i < n) {
                g_start[i] = run;
                g_cursor[i] = run;
                ull pk = g_packed[i];
                float deg = (float)(pk & (((ull)1 << 40) - 1)) * (1.0f / 268435456.0f);
                g_dinv[i] = rsqrtf(deg);
                run += (int)(pk >> 40);
            }
        }
    }
}

__global__ void build_kernel(const void* __restrict__ ei,
                             const float* __restrict__ ew, int E, int n)
{
    int e = blockIdx.x * blockDim.x + threadIdx.x;
    if (e < E) {
        int r = edge_at(ei, e);
        int c = edge_at(ei, E + e);
        if ((unsigned)r < (unsigned)n && (unsigned)c < (unsigned)n) {
            float nm = g_dinv[r] * ew[e] * g_dinv[c];
            int p = atomicAdd(&g_cursor[c], 1);
            if ((unsigned)p < (unsigned)EMAX)
                g_edge[p] = make_uint2((unsigned)r, __float_as_uint(nm));
        }
    }
}

// ---------------------------------------------------------------------------
// Tensor-core GEMM v2: g_S = g_Hh @ W (fp16 x fp16 -> fp32), no staging.
// 8 warps/block, grid-strided over 16-row tiles. C stored direct to global.
// ---------------------------------------------------------------------------
__global__ void __launch_bounds__(256) gemm_wmma_kernel(const float* __restrict__ W,
                                                        int ntiles)
{
    __shared__ __half sW[64 * 64];
    int t = threadIdx.x;
    for (int i = t; i < 4096; i += 256) sW[i] = __float2half(W[i]);
    __syncthreads();

    int warp = t >> 5;

    for (int tile = blockIdx.x * 8 + warp; tile < ntiles; tile += gridDim.x * 8) {
        int row0 = tile * 16;

        wmma::fragment<wmma::accumulator, 16, 16, 16, float> c[4];
#pragma unroll
        for (int j = 0; j < 4; j++) wmma::fill_fragment(c[j], 0.0f);

#pragma unroll
        for (int k = 0; k < 4; k++) {
            wmma::fragment<wmma::matrix_a, 16, 16, 16, __half, wmma::row_major> a;
            wmma::load_matrix_sync(a, g_Hh + (size_t)row0 * 64 + k * 16, 64);
#pragma unroll
            for (int j = 0; j < 4; j++) {
                wmma::fragment<wmma::matrix_b, 16, 16, 16, __half, wmma::row_major> b;
                wmma::load_matrix_sync(b, sW + (k * 16) * 64 + j * 16, 64);
                wmma::mma_sync(c[j], a, b, c[j]);
            }
        }

#pragma unroll
        for (int j = 0; j < 4; j++)
            wmma::store_matrix_sync(g_S + (size_t)row0 * 64 + j * 16, c[j], 64,
                                    wmma::mem_row_major);
    }
}

// ---------------------------------------------------------------------------
// Aggregation core: warp/node, fp32 float2 gather from g_S, unroll-4 + tail.
// ---------------------------------------------------------------------------
__device__ __forceinline__ float2 agg_node(int i, int lane)
{
    const float2* hw2 = reinterpret_cast<const float2*>(g_S);
    float di = g_dinv[i];
    float selfn = di * di;
    float2 v = hw2[(size_t)i * 32 + lane];
    float ax = selfn * v.x, ay = selfn * v.y;
    float a1x = 0.f, a1y = 0.f, a2x = 0.f, a2y = 0.f, a3x = 0.f, a3y = 0.f;

    int e = g_start[i];
    int end = e + (int)(g_packed[i] >> 40);
    for (; e + 4 <= end; e += 4) {
        uint2 e0 = g_edge[e], e1 = g_edge[e + 1], e2 = g_edge[e + 2], e3 = g_edge[e + 3];
        float2 v0 = hw2[(size_t)e0.x * 32 + lane];
        float2 v1 = hw2[(size_t)e1.x * 32 + lane];
        float2 v2 = hw2[(size_t)e2.x * 32 + lane];
        float2 v3 = hw2[(size_t)e3.x * 32 + lane];
        float n0 = __uint_as_float(e0.y), n1 = __uint_as_float(e1.y);
        float n2 = __uint_as_float(e2.y), n3 = __uint_as_float(e3.y);
        ax  += n0 * v0.x; ay  += n0 * v0.y;
        a1x += n1 * v1.x; a1y += n1 * v1.y;
        a2x += n2 * v2.x; a2y += n2 * v2.y;
        a3x += n3 * v3.x; a3y += n3 * v3.y;
    }
    for (; e < end; e++) {
        uint2 e0 = g_edge[e];
        float2 v0 = hw2[(size_t)e0.x * 32 + lane];
        float n0 = __uint_as_float(e0.y);
        ax += n0 * v0.x; ay += n0 * v0.y;
    }
    ax += a1x + a2x + a3x;
    ay += a1y + a2y + a3y;
    return make_float2(ax, ay);
}

// layers 1,2: write fp32 h to g_H[dst] AND fp16 h to g_Hh (next GEMM's A)
__global__ void __launch_bounds__(256) agg_kernel(const float* __restrict__ bias,
                                                  int resid, int dst, int n)
{
    int wid = (blockIdx.x * blockDim.x + threadIdx.x) >> 5;
    int lane = threadIdx.x & 31;
    if (wid >= n) return;

    float2 a = agg_node(wid, lane);
    float2 bb = reinterpret_cast<const float2*>(bias)[lane];
    a.x += bb.x; a.y += bb.y;
    if (resid >= 0) {
        float2 r = reinterpret_cast<const float2*>(g_H[resid])[(size_t)wid * 32 + lane];
        a.x += r.x; a.y += r.y;
    }
    a.x = fmaxf(a.x, 0.f); a.y = fmaxf(a.y, 0.f);
    reinterpret_cast<float2*>(g_H[dst])[(size_t)wid * 32 + lane] = a;
    __half2 hh = __floats2half2_rn(a.x, a.y);
    reinterpret_cast<__half2*>(g_Hh)[(size_t)wid * 32 + lane] = hh;
}

// layer 3 fused with final GEMV: F[i] = relu(agg + b2 + h2) . Wf
__global__ void __launch_bounds__(256) agg3_kernel(const float* __restrict__ bias,
                                                   int resid,
                                                   const float* __restrict__ Wf, int n)
{
    int wid = (blockIdx.x * blockDim.x + threadIdx.x) >> 5;
    int lane = threadIdx.x & 31;
    if (wid >= n) return;

    float2 a = agg_node(wid, lane);
    float2 bb = reinterpret_cast<const float2*>(bias)[lane];
    a.x += bb.x; a.y += bb.y;
    if (resid >= 0) {
        float2 r = reinterpret_cast<const float2*>(g_H[resid])[(size_t)wid * 32 + lane];
        a.x += r.x; a.y += r.y;
    }
    a.x = fmaxf(a.x, 0.f); a.y = fmaxf(a.y, 0.f);

    float2 wf = reinterpret_cast<const float2*>(Wf)[lane];
    float p = a.x * wf.x + a.y * wf.y;
#pragma unroll
    for (int o = 16; o; o >>= 1) p += __shfl_xor_sync(0xffffffffu, p, o);
    if (lane == 0) g_F[wid] = p;
}

// ---------------------------------------------------------------------------
// Final scalar aggregation
// ---------------------------------------------------------------------------
__global__ void agg_final_kernel(const float* __restrict__ bf,
                                 float* __restrict__ out, int n)
{
    int i = blockIdx.x * blockDim.x + threadIdx.x;
    if (i >= n) return;
    float di = g_dinv[i];
    float acc = di * di * g_F[i];
    float a1 = 0.f, a2 = 0.f, a3 = 0.f;
    int e = g_start[i];
    int end = e + (int)(g_packed[i] >> 40);
    for (; e + 4 <= end; e += 4) {
        uint2 e0 = g_edge[e], e1 = g_edge[e + 1], e2 = g_edge[e + 2], e3 = g_edge[e + 3];
        acc += __uint_as_float(e0.y) * g_F[e0.x];
        a1  += __uint_as_float(e1.y) * g_F[e1.x];
        a2  += __uint_as_float(e2.y) * g_F[e2.x];
        a3  += __uint_as_float(e3.y) * g_F[e3.x];
    }
    for (; e < end; e++) {
        uint2 e0 = g_edge[e];
        acc += __uint_as_float(e0.y) * g_F[e0.x];
    }
    out[i] = acc + a1 + a2 + a3 + bf[0];
}

// ---------------------------------------------------------------------------
// Launch
// ---------------------------------------------------------------------------
extern "C" void kernel_launch(void* const* d_in, const int* in_sizes, int n_in,
                              void* d_out, int out_size)
{
    const float* x    = (const float*)d_in[0];
    const void*  ei   = d_in[1];
    const float* ew   = (const float*)d_in[2];
    const float* W_in = (const float*)d_in[4];
    const float* b_in = (const float*)d_in[5];
    const float* W1   = (const float*)d_in[6];
    const float* b1   = (const float*)d_in[7];
    const float* W2   = (const float*)d_in[8];
    const float* b2   = (const float*)d_in[9];
    const float* Wf   = (const float*)d_in[10];
    const float* bf   = (const float*)d_in[11];
    float* out = (float*)d_out;

    int n = in_sizes[0] / 64;
    int E = in_sizes[2];

    int nbN  = (n + 255) / 256;
    int nbE  = (E + 255) / 256;
    int nbSc = (n + 1023) / 1024;       // <= NTILES
    int nbAg = (n + 7) / 8;             // warp per node, 8 warps/block
    int nbCv = (n * 16 + 255) / 256;    // float4 units
    int ntiles = (n + 15) / 16;         // 16-row wmma tiles
    int nbGw = 148;                     // one block per SM, grid-strided

    // --- ordering: wmma GEMM at launch idx 3 for ncu capture ---
    convert_kernel<<<nbCv, 256>>>(x, n * 16);            // 0: x -> fp16
    init_kernel<<<nbN, 256>>>(ei, E, n);                 // 1
    hist_kernel<<<nbE, 256>>>(ei, ew, E, n);             // 2
    gemm_wmma_kernel<<<nbGw, 256>>>(W_in, ntiles);       // 3: layer-1 GEMM
    scan_kernel<<<nbSc, 256>>>(n);                       // 4
    build_kernel<<<nbE, 256>>>(ei, ew, E, n);            // 5

    // --- layer 1: h1 = relu(conv(x)) -> H[0], g_Hh ---
    agg_kernel<<<nbAg, 256>>>(b_in, -1, 0, n);

    // --- layer 2: h2 = relu(conv(h1) + h1) -> H[1], g_Hh ---
    gemm_wmma_kernel<<<nbGw, 256>>>(W1, ntiles);
    agg_kernel<<<nbAg, 256>>>(b1, 0, 1, n);

    // --- layer 3 + final gemv: F = relu(conv(h2)+h2) . Wf ---
    gemm_wmma_kernel<<<nbGw, 256>>>(W2, ntiles);
    agg3_kernel<<<nbAg, 256>>>(b2, 1, Wf, n);

    // --- final aggregation ---
    agg_final_kernel<<<nbN, 256>>>(bf, out, n);
}

// round 8
// speedup vs baseline: 1.2990x; 1.0012x over previous
#include <cuda_runtime.h>
#include <cuda_fp16.h>
#include <mma.h>
#include <stdint.h>

using namespace nvcuda;

#define NMAX 100000
#define EMAX 1000000
#define NTILES 128   // >= ceil(NMAX/1024)
#define NPAD (NMAX + 128)

typedef unsigned long long ull;

// ---- static device scratch ----
__device__ __align__(16) ull    g_packed[NMAX];     // count<<40 | deg_fixed(2^-28)
__device__ __align__(16) int    g_start[NMAX];
__device__ __align__(16) int    g_cursor[NMAX];
__device__ __align__(16) ull    g_status[NTILES];   // lookback: flag(2) | sum<<2
__device__ __align__(16) float  g_dinv[NMAX];
__device__ __align__(16) uint2  g_edge[EMAX];       // (src, norm bits)
__device__ __align__(16) __half g_Hh[NPAD * 64];    // fp16 h (GEMM A input)
__device__ __align__(16) float  g_S[NPAD * 64];     // hw = h@W, fp32 (GEMM C output)
__device__ __align__(16) float  g_H[2][NMAX * 64];  // h1 / h2 fp32 (residuals)
__device__ __align__(16) float  g_F[NMAX];          // final gemv result
__device__ int g_is64;

// ---------------------------------------------------------------------------
__device__ __forceinline__ int edge_at(const void* ei, int idx)
{
    if (g_is64) return (int)((const long long*)ei)[idx];
    return ((const int*)ei)[idx];
}

// ---------------------------------------------------------------------------
// fused: x fp32 -> g_Hh fp16 conversion  +  init (probe, status, packed)
// ---------------------------------------------------------------------------
__global__ void convert_init_kernel(const float* __restrict__ x, int total4,
                                    const void* ei, int n)
{
    int i = blockIdx.x * blockDim.x + threadIdx.x;
    if (blockIdx.x == 0 && threadIdx.x < 32) {
        long long v = ((const long long*)ei)[threadIdx.x];
        unsigned ok = __ballot_sync(0xffffffffu, v >= 0 && v < (long long)n);
        if (threadIdx.x == 0) g_is64 = (ok == 0xffffffffu) ? 1 : 0;
    }
    if (i < NTILES) g_status[i] = 0;
    if (i < n) g_packed[i] = (ull)1 << 28;   // self-loop deg 1.0 in 2^-28 fixed
    if (i < total4) {
        float4 v = reinterpret_cast<const float4*>(x)[i];
        __half2 lo = __floats2half2_rn(v.x, v.y);
        __half2 hi = __floats2half2_rn(v.z, v.w);
        uint2 o;
        o.x = *reinterpret_cast<unsigned*>(&lo);
        o.y = *reinterpret_cast<unsigned*>(&hi);
        reinterpret_cast<uint2*>(g_Hh)[i] = o;
    }
}

__global__ void hist_kernel(const void* __restrict__ ei,
                            const float* __restrict__ ew, int E, int n)
{
    int e = blockIdx.x * blockDim.x + threadIdx.x;
    if (e < E) {
        int c = edge_at(ei, E + e);
        if ((unsigned)c < (unsigned)n) {
            ull add = ((ull)1 << 40) + __float2ull_rn(ew[e] * 268435456.0f);
            atomicAdd(&g_packed[c], add);
        }
    }
}

// ---------------------------------------------------------------------------
// single-pass scan (decoupled lookback, tile=1024) + cursor/dinv
// ---------------------------------------------------------------------------
__global__ void __launch_bounds__(256) scan_kernel(int n)
{
    __shared__ int sd[256];
    __shared__ int s_excl;
    int t = threadIdx.x;
    int b = blockIdx.x;
    int base = b * 1024 + t * 4;

    int v0 = (base + 0 < n) ? (int)(g_packed[base + 0] >> 40) : 0;
    int v1 = (base + 1 < n) ? (int)(g_packed[base + 1] >> 40) : 0;
    int v2 = (base + 2 < n) ? (int)(g_packed[base + 2] >> 40) : 0;
    int v3 = (base + 3 < n) ? (int)(g_packed[base + 3] >> 40) : 0;
    int tsum = v0 + v1 + v2 + v3;
    sd[t] = tsum;
    __syncthreads();
    int x = tsum;
    for (int off = 1; off < 256; off <<= 1) {
        int y = (t >= off) ? sd[t - off] : 0;
        __syncthreads();
        x += y;
        sd[t] = x;
        __syncthreads();
    }
    int thr_excl = x - tsum;
    int agg = sd[255];
    __syncthreads();

    if (t == 0) {
        ull st = b == 0 ? (2ull | ((ull)agg << 2)) : (1ull | ((ull)agg << 2));
        atomicExch(&g_status[b], st);
    }

    if (t < 32) {
        int excl = 0;
        if (b > 0) {
            int j = b - 1;
            for (;;) {
                int idx = j - (int)t;
                ull st = 0;
                if (idx >= 0) {
                    do { st = atomicAdd(&g_status[idx], 0ull); } while ((st & 3ull) == 0ull);
                }
                unsigned pmask = __ballot_sync(0xffffffffu, idx >= 0 && (st & 3ull) == 2ull);
                int val = (int)(st >> 2);
                if (pmask) {
                    int lead = __ffs(pmask) - 1;
                    int contrib = (t <= lead && idx >= 0) ? val : 0;
                    for (int o = 16; o; o >>= 1) contrib += __shfl_xor_sync(0xffffffffu, contrib, o);
                    excl += contrib;
                    break;
                } else {
                    int contrib = (idx >= 0) ? val : 0;
                    for (int o = 16; o; o >>= 1) contrib += __shfl_xor_sync(0xffffffffu, contrib, o);
                    excl += contrib;
                    j -= 32;
                }
            }
            if (t == 0) atomicExch(&g_status[b], 2ull | ((ull)(excl + agg) << 2));
        }
        if (t == 0) s_excl = excl;
    }
    __syncthreads();

    int run = s_excl + thr_excl;
    if (base < n) {
#pragma unroll
        for (int q = 0; q < 4; q++) {
            int i = base + q;
            if (i < n) {
                g_start[i] = run;
                g_cursor[i] = run;
                ull pk = g_packed[i];
                float deg = (float)(pk & (((ull)1 << 40) - 1)) * (1.0f / 268435456.0f);
                g_dinv[i] = rsqrtf(deg);
                run += (int)(pk >> 40);
            }
        }
    }
}

__global__ void build_kernel(const void* __restrict__ ei,
                             const float* __restrict__ ew, int E, int n)
{
    int e = blockIdx.x * blockDim.x + threadIdx.x;
    if (e < E) {
        int r = edge_at(ei, e);
        int c = edge_at(ei, E + e);
        if ((unsigned)r < (unsigned)n && (unsigned)c < (unsigned)n) {
            float nm = g_dinv[r] * ew[e] * g_dinv[c];
            int p = atomicAdd(&g_cursor[c], 1);
            if ((unsigned)p < (unsigned)EMAX)
                g_edge[p] = make_uint2((unsigned)r, __float_as_uint(nm));
        }
    }
}

// ---------------------------------------------------------------------------
// Tensor-core GEMM: g_S = g_Hh @ W (fp16 x fp16 -> fp32), direct global C.
// grid-strided 16-row tiles; 592 blocks (4/SM) for latency hiding.
// ---------------------------------------------------------------------------
__global__ void __launch_bounds__(256) gemm_wmma_kernel(const float* __restrict__ W,
                                                        int ntiles)
{
    __shared__ __half sW[64 * 64];
    int t = threadIdx.x;
    for (int i = t; i < 4096; i += 256) sW[i] = __float2half(W[i]);
    __syncthreads();

    int warp = t >> 5;

    for (int tile = blockIdx.x * 8 + warp; tile < ntiles; tile += gridDim.x * 8) {
        int row0 = tile * 16;

        wmma::fragment<wmma::accumulator, 16, 16, 16, float> c[4];
#pragma unroll
        for (int j = 0; j < 4; j++) wmma::fill_fragment(c[j], 0.0f);

#pragma unroll
        for (int k = 0; k < 4; k++) {
            wmma::fragment<wmma::matrix_a, 16, 16, 16, __half, wmma::row_major> a;
            wmma::load_matrix_sync(a, g_Hh + (size_t)row0 * 64 + k * 16, 64);
#pragma unroll
            for (int j = 0; j < 4; j++) {
                wmma::fragment<wmma::matrix_b, 16, 16, 16, __half, wmma::row_major> b;
                wmma::load_matrix_sync(b, sW + (k * 16) * 64 + j * 16, 64);
                wmma::mma_sync(c[j], a, b, c[j]);
            }
        }

#pragma unroll
        for (int j = 0; j < 4; j++)
            wmma::store_matrix_sync(g_S + (size_t)row0 * 64 + j * 16, c[j], 64,
                                    wmma::mem_row_major);
    }
}

// ---------------------------------------------------------------------------
// Aggregation core: warp/node, fp32 float2 gather from g_S, unroll-4 + tail.
// ---------------------------------------------------------------------------
__device__ __forceinline__ float2 agg_node(int i, int lane)
{
    const float2* hw2 = reinterpret_cast<const float2*>(g_S);
    float di = g_dinv[i];
    float selfn = di * di;
    float2 v = hw2[(size_t)i * 32 + lane];
    float ax = selfn * v.x, ay = selfn * v.y;
    float a1x = 0.f, a1y = 0.f, a2x = 0.f, a2y = 0.f, a3x = 0.f, a3y = 0.f;

    int e = g_start[i];
    int end = e + (int)(g_packed[i] >> 40);
    for (; e + 4 <= end; e += 4) {
        uint2 e0 = g_edge[e], e1 = g_edge[e + 1], e2 = g_edge[e + 2], e3 = g_edge[e + 3];
        float2 v0 = hw2[(size_t)e0.x * 32 + lane];
        float2 v1 = hw2[(size_t)e1.x * 32 + lane];
        float2 v2 = hw2[(size_t)e2.x * 32 + lane];
        float2 v3 = hw2[(size_t)e3.x * 32 + lane];
        float n0 = __uint_as_float(e0.y), n1 = __uint_as_float(e1.y);
        float n2 = __uint_as_float(e2.y), n3 = __uint_as_float(e3.y);
        ax  += n0 * v0.x; ay  += n0 * v0.y;
        a1x += n1 * v1.x; a1y += n1 * v1.y;
        a2x += n2 * v2.x; a2y += n2 * v2.y;
        a3x += n3 * v3.x; a3y += n3 * v3.y;
    }
    for (; e < end; e++) {
        uint2 e0 = g_edge[e];
        float2 v0 = hw2[(size_t)e0.x * 32 + lane];
        float n0 = __uint_as_float(e0.y);
        ax += n0 * v0.x; ay += n0 * v0.y;
    }
    ax += a1x + a2x + a3x;
    ay += a1y + a2y + a3y;
    return make_float2(ax, ay);
}

// layers 1,2: write fp32 h to g_H[dst] AND fp16 h to g_Hh (next GEMM's A)
__global__ void __launch_bounds__(256) agg_kernel(const float* __restrict__ bias,
                                                  int resid, int dst, int n)
{
    int wid = (blockIdx.x * blockDim.x + threadIdx.x) >> 5;
    int lane = threadIdx.x & 31;
    if (wid >= n) return;

    float2 a = agg_node(wid, lane);
    float2 bb = reinterpret_cast<const float2*>(bias)[lane];
    a.x += bb.x; a.y += bb.y;
    if (resid >= 0) {
        float2 r = reinterpret_cast<const float2*>(g_H[resid])[(size_t)wid * 32 + lane];
        a.x += r.x; a.y += r.y;
    }
    a.x = fmaxf(a.x, 0.f); a.y = fmaxf(a.y, 0.f);
    reinterpret_cast<float2*>(g_H[dst])[(size_t)wid * 32 + lane] = a;
    __half2 hh = __floats2half2_rn(a.x, a.y);
    reinterpret_cast<__half2*>(g_Hh)[(size_t)wid * 32 + lane] = hh;
}

// layer 3 fused with final GEMV: F[i] = relu(agg + b2 + h2) . Wf
__global__ void __launch_bounds__(256) agg3_kernel(const float* __restrict__ bias,
                                                   int resid,
                                                   const float* __restrict__ Wf, int n)
{
    int wid = (blockIdx.x * blockDim.x + threadIdx.x) >> 5;
    int lane = threadIdx.x & 31;
    if (wid >= n) return;

    float2 a = agg_node(wid, lane);
    float2 bb = reinterpret_cast<const float2*>(bias)[lane];
    a.x += bb.x; a.y += bb.y;
    if (resid >= 0) {
        float2 r = reinterpret_cast<const float2*>(g_H[resid])[(size_t)wid * 32 + lane];
        a.x += r.x; a.y += r.y;
    }
    a.x = fmaxf(a.x, 0.f); a.y = fmaxf(a.y, 0.f);

    float2 wf = reinterpret_cast<const float2*>(Wf)[lane];
    float p = a.x * wf.x + a.y * wf.y;
#pragma unroll
    for (int o = 16; o; o >>= 1) p += __shfl_xor_sync(0xffffffffu, p, o);
    if (lane == 0) g_F[wid] = p;
}

// ---------------------------------------------------------------------------
// Final scalar aggregation
// ---------------------------------------------------------------------------
__global__ void agg_final_kernel(const float* __restrict__ bf,
                                 float* __restrict__ out, int n)
{
    int i = blockIdx.x * blockDim.x + threadIdx.x;
    if (i >= n) return;
    float di = g_dinv[i];
    float acc = di * di * g_F[i];
    float a1 = 0.f, a2 = 0.f, a3 = 0.f;
    int e = g_start[i];
    int end = e + (int)(g_packed[i] >> 40);
    for (; e + 4 <= end; e += 4) {
        uint2 e0 = g_edge[e], e1 = g_edge[e + 1], e2 = g_edge[e + 2], e3 = g_edge[e + 3];
        acc += __uint_as_float(e0.y) * g_F[e0.x];
        a1  += __uint_as_float(e1.y) * g_F[e1.x];
        a2  += __uint_as_float(e2.y) * g_F[e2.x];
        a3  += __uint_as_float(e3.y) * g_F[e3.x];
    }
    for (; e < end; e++) {
        uint2 e0 = g_edge[e];
        acc += __uint_as_float(e0.y) * g_F[e0.x];
    }
    out[i] = acc + a1 + a2 + a3 + bf[0];
}

// ---------------------------------------------------------------------------
// Launch
// ---------------------------------------------------------------------------
extern "C" void kernel_launch(void* const* d_in, const int* in_sizes, int n_in,
                              void* d_out, int out_size)
{
    const float* x    = (const float*)d_in[0];
    const void*  ei   = d_in[1];
    const float* ew   = (const float*)d_in[2];
    const float* W_in = (const float*)d_in[4];
    const float* b_in = (const float*)d_in[5];
    const float* W1   = (const float*)d_in[6];
    const float* b1   = (const float*)d_in[7];
    const float* W2   = (const float*)d_in[8];
    const float* b2   = (const float*)d_in[9];
    const float* Wf   = (const float*)d_in[10];
    const float* bf   = (const float*)d_in[11];
    float* out = (float*)d_out;

    int n = in_sizes[0] / 64;
    int E = in_sizes[2];

    int nbN  = (n + 255) / 256;
    int nbE  = (E + 255) / 256;
    int nbSc = (n + 1023) / 1024;       // <= NTILES
    int nbAg = (n + 7) / 8;             // warp per node, 8 warps/block
    int nbCv = (n * 16 + 255) / 256;    // float4 units (covers init too)
    int ntiles = (n + 15) / 16;         // 16-row wmma tiles
    int nbGw = 592;                     // 4 blocks per SM, grid-strided

    // --- CSR build; wmma GEMM at launch idx 3 for ncu capture ---
    convert_init_kernel<<<nbCv, 256>>>(x, n * 16, ei, n);   // 0
    hist_kernel<<<nbE, 256>>>(ei, ew, E, n);                // 1
    scan_kernel<<<nbSc, 256>>>(n);                          // 2
    gemm_wmma_kernel<<<nbGw, 256>>>(W_in, ntiles);          // 3 (profiled)
    build_kernel<<<nbE, 256>>>(ei, ew, E, n);               // 4

    // --- layer 1: h1 = relu(conv(x)) -> H[0], g_Hh ---
    agg_kernel<<<nbAg, 256>>>(b_in, -1, 0, n);

    // --- layer 2: h2 = relu(conv(h1) + h1) -> H[1], g_Hh ---
    gemm_wmma_kernel<<<nbGw, 256>>>(W1, ntiles);
    agg_kernel<<<nbAg, 256>>>(b1, 0, 1, n);

    // --- layer 3 + final gemv: F = relu(conv(h2)+h2) . Wf ---
    gemm_wmma_kernel<<<nbGw, 256>>>(W2, ntiles);
    agg3_kernel<<<nbAg, 256>>>(b2, 1, Wf, n);

    // --- final aggregation ---
    agg_final_kernel<<<nbN, 256>>>(bf, out, n);
}